// round 3
// baseline (speedup 1.0000x reference)
#include <cuda_runtime.h>
#include <cuda_bf16.h>

// DinoPool == masked average pooling of x over 512-row blocks.
// x: [B=4, S=4096, C=384] fp32 -> out same shape.
// out[b, s, c] = mean_{r in block(s)} x[b, r, c].
//
// R3: split into reduce + broadcast kernels to kill the per-CTA
// read->barrier->write serialization and cover all 148 SMs.
//  K1: 768 CTAs, each sums 64 rows x 128 cols -> partial sums in L2 scratch.
//  K2: 768 CTAs, each finishes the mean (8 partials, L2-hot) and writes
//      64 output rows. Deterministic (no atomics).

static constexpr int S      = 4096;
static constexpr int C      = 384;     // H*D
static constexpr int C4     = C / 4;   // 96 float4 per row
static constexpr int BLOCK  = 512;
static constexpr int NSEG   = 8;       // row segments per block
static constexpr int SEGROWS = BLOCK / NSEG;   // 64
static constexpr int CHUNK4 = 32;      // float4 columns per CTA
static constexpr int NTHREADS = 256;
static constexpr int ROWGRPS = NTHREADS / CHUNK4;        // 8
static constexpr int RPT     = SEGROWS / ROWGRPS;        // 8 rows per thread
static constexpr int NBAT   = 4;
static constexpr int NBLK   = S / BLOCK;                 // 8

// partial sums: [bat][blk][seg][C4] float4
__device__ float4 g_partial[NBAT * NBLK * NSEG * C4];

__global__ __launch_bounds__(NTHREADS, 8)
void dinopool_reduce(const float* __restrict__ x) {
    const int chunk = blockIdx.x;            // 0..2
    const int blk   = blockIdx.y;            // 0..7
    const int bat   = blockIdx.z >> 3;       // 0..3
    const int seg   = blockIdx.z & 7;        // 0..7

    const int c  = threadIdx.x & (CHUNK4 - 1);
    const int rg = threadIdx.x >> 5;

    const float4* __restrict__ x4 = reinterpret_cast<const float4*>(x);

    const size_t base = ((size_t)bat * S + (size_t)blk * BLOCK
                         + (size_t)seg * SEGROWS + (size_t)rg * RPT) * C4
                        + (size_t)chunk * CHUNK4 + c;

    float4 acc = make_float4(0.f, 0.f, 0.f, 0.f);
    #pragma unroll
    for (int r = 0; r < RPT; r++) {
        float4 v = __ldg(&x4[base + (size_t)r * C4]);
        acc.x += v.x; acc.y += v.y; acc.z += v.z; acc.w += v.w;
    }

    __shared__ float4 smem[ROWGRPS][CHUNK4];
    smem[rg][c] = acc;
    __syncthreads();

    if (threadIdx.x < CHUNK4) {
        float4 t = smem[0][c];
        #pragma unroll
        for (int i = 1; i < ROWGRPS; i++) {
            float4 v = smem[i][c];
            t.x += v.x; t.y += v.y; t.z += v.z; t.w += v.w;
        }
        const int pidx = (((bat * NBLK + blk) * NSEG) + seg) * C4
                         + chunk * CHUNK4 + c;
        g_partial[pidx] = t;
    }
}

__global__ __launch_bounds__(NTHREADS, 8)
void dinopool_broadcast(float* __restrict__ out) {
    const int chunk = blockIdx.x;            // 0..2
    const int blk   = blockIdx.y;            // 0..7
    const int bat   = blockIdx.z >> 3;       // 0..3
    const int oseg  = blockIdx.z & 7;        // output row segment 0..7

    const int c  = threadIdx.x & (CHUNK4 - 1);
    const int rg = threadIdx.x >> 5;

    // finish the mean for column (chunk*32 + c): sum 8 partials (L2-hot)
    const int pbase = ((bat * NBLK + blk) * NSEG) * C4 + chunk * CHUNK4 + c;
    float4 t = g_partial[pbase];
    #pragma unroll
    for (int s = 1; s < NSEG; s++) {
        float4 v = g_partial[pbase + s * C4];
        t.x += v.x; t.y += v.y; t.z += v.z; t.w += v.w;
    }
    const float inv = 1.0f / (float)BLOCK;
    t.x *= inv; t.y *= inv; t.z *= inv; t.w *= inv;

    float4* __restrict__ o4 = reinterpret_cast<float4*>(out);
    const size_t base = ((size_t)bat * S + (size_t)blk * BLOCK
                         + (size_t)oseg * SEGROWS + (size_t)rg * RPT) * C4
                        + (size_t)chunk * CHUNK4 + c;
    #pragma unroll
    for (int i = 0; i < RPT; i++) {
        o4[base + (size_t)i * C4] = t;
    }
}

extern "C" void kernel_launch(void* const* d_in, const int* in_sizes, int n_in,
                              void* d_out, int out_size) {
    const float* x = (const float*)d_in[0];   // [4, 4096, 384] fp32
    float* out     = (float*)d_out;
    (void)in_sizes; (void)n_in; (void)out_size;

    dim3 grid(C4 / CHUNK4 /*3*/, NBLK /*8*/, NBAT * NSEG /*32*/);
    dinopool_reduce<<<grid, NTHREADS>>>(x);
    dinopool_broadcast<<<grid, NTHREADS>>>(out);
}

// round 4
// speedup vs baseline: 1.0201x; 1.0201x over previous
#include <cuda_runtime.h>
#include <cuda_bf16.h>
#include <cstdint>

// DinoPool == masked average pooling of x over 512-row blocks.
// x: [B=4, S=4096, C=384] fp32 -> out same shape.
// out[b, s, c] = mean_{r in block(s)} x[b, r, c].
//
// R4: K1 reduce (LDG, DRAM-read-bound) unchanged from R3.
//     K2 store rewritten to use TMA bulk copies (cp.async.bulk S->G):
//     each CTA builds a 32-row replicated mean tile in smem (48KB) and
//     issues 2 x 48KB bulk stores covering 64 contiguous output rows,
//     bypassing the per-thread STG path that measured 8.1us.

static constexpr int S        = 4096;
static constexpr int C        = 384;     // H*D
static constexpr int C4       = C / 4;   // 96 float4 per row
static constexpr int BLOCK    = 512;
static constexpr int NBAT     = 4;
static constexpr int NBLK     = S / BLOCK;   // 8

// K1 segmentation
static constexpr int NSEG     = 8;
static constexpr int SEGROWS  = BLOCK / NSEG;        // 64
static constexpr int CHUNK4   = 32;
static constexpr int NT1      = 256;
static constexpr int ROWGRPS  = NT1 / CHUNK4;        // 8
static constexpr int RPT      = SEGROWS / ROWGRPS;   // 8

// K2 tiling
static constexpr int OSEG      = 8;      // 8 output segments of 64 rows
static constexpr int OSEGROWS  = BLOCK / OSEG;       // 64
static constexpr int TILE_ROWS = 32;     // rows replicated in smem
static constexpr int TILE_BYTES = TILE_ROWS * C * 4; // 49152 = 48KB
static constexpr int NT2       = 256;

// partial sums: [bat][blk][seg][C4] float4
__device__ float4 g_partial[NBAT * NBLK * NSEG * C4];

__global__ __launch_bounds__(NT1, 8)
void dinopool_reduce(const float* __restrict__ x) {
    const int chunk = blockIdx.x;            // 0..2
    const int blk   = blockIdx.y;            // 0..7
    const int bat   = blockIdx.z >> 3;       // 0..3
    const int seg   = blockIdx.z & 7;        // 0..7

    const int c  = threadIdx.x & (CHUNK4 - 1);
    const int rg = threadIdx.x >> 5;

    const float4* __restrict__ x4 = reinterpret_cast<const float4*>(x);

    const size_t base = ((size_t)bat * S + (size_t)blk * BLOCK
                         + (size_t)seg * SEGROWS + (size_t)rg * RPT) * C4
                        + (size_t)chunk * CHUNK4 + c;

    float4 acc = make_float4(0.f, 0.f, 0.f, 0.f);
    #pragma unroll
    for (int r = 0; r < RPT; r++) {
        float4 v = __ldg(&x4[base + (size_t)r * C4]);
        acc.x += v.x; acc.y += v.y; acc.z += v.z; acc.w += v.w;
    }

    __shared__ float4 smem[ROWGRPS][CHUNK4];
    smem[rg][c] = acc;
    __syncthreads();

    if (threadIdx.x < CHUNK4) {
        float4 t = smem[0][c];
        #pragma unroll
        for (int i = 1; i < ROWGRPS; i++) {
            float4 v = smem[i][c];
            t.x += v.x; t.y += v.y; t.z += v.z; t.w += v.w;
        }
        const int pidx = (((bat * NBLK + blk) * NSEG) + seg) * C4
                         + chunk * CHUNK4 + c;
        g_partial[pidx] = t;
    }
}

__global__ __launch_bounds__(NT2, 4)
void dinopool_store(float* __restrict__ out) {
    const int blk  = blockIdx.x;             // 0..7
    const int bat  = blockIdx.y;             // 0..3
    const int oseg = blockIdx.z;             // 0..7  (64 output rows each)

    __shared__ __align__(16) float4 tile[TILE_ROWS * C4];   // 48KB

    // ---- finish the mean row: sum 8 partials per column (L2-hot) ----
    const int t = threadIdx.x;
    if (t < C4) {
        const int pbase = ((bat * NBLK + blk) * NSEG) * C4 + t;
        float4 m = g_partial[pbase];
        #pragma unroll
        for (int s = 1; s < NSEG; s++) {
            float4 v = g_partial[pbase + s * C4];
            m.x += v.x; m.y += v.y; m.z += v.z; m.w += v.w;
        }
        const float inv = 1.0f / (float)BLOCK;
        m.x *= inv; m.y *= inv; m.z *= inv; m.w *= inv;
        tile[t] = m;                         // row 0 of the tile
    }
    __syncthreads();

    // ---- replicate the mean row into all TILE_ROWS rows ----
    for (int i = C4 + t; i < TILE_ROWS * C4; i += NT2) {
        tile[i] = tile[i % C4];
    }
    __syncthreads();

    // ---- bulk-store the tile twice to cover 64 contiguous output rows ----
    if (t == 0) {
        asm volatile("fence.proxy.async.shared::cta;" ::: "memory");
        uint32_t saddr = (uint32_t)__cvta_generic_to_shared(tile);
        char* gbase = (char*)out
            + ((size_t)bat * S + (size_t)blk * BLOCK + (size_t)oseg * OSEGROWS)
              * (size_t)C * 4;
        #pragma unroll
        for (int j = 0; j < OSEGROWS / TILE_ROWS; j++) {   // 2 copies
            asm volatile(
                "cp.async.bulk.global.shared::cta.bulk_group [%0], [%1], %2;"
                :: "l"(gbase + (size_t)j * TILE_BYTES), "r"(saddr),
                   "r"((int)TILE_BYTES)
                : "memory");
        }
        asm volatile("cp.async.bulk.commit_group;" ::: "memory");
        asm volatile("cp.async.bulk.wait_group 0;" ::: "memory");
    }
}

extern "C" void kernel_launch(void* const* d_in, const int* in_sizes, int n_in,
                              void* d_out, int out_size) {
    const float* x = (const float*)d_in[0];   // [4, 4096, 384] fp32
    float* out     = (float*)d_out;
    (void)in_sizes; (void)n_in; (void)out_size;

    dim3 g1(C4 / CHUNK4 /*3*/, NBLK /*8*/, NBAT * NSEG /*32*/);
    dinopool_reduce<<<g1, NT1>>>(x);

    dim3 g2(NBLK /*8*/, NBAT /*4*/, OSEG /*8*/);
    dinopool_store<<<g2, NT2>>>(out);
}